// round 12
// baseline (speedup 1.0000x reference)
#include <cuda_runtime.h>
#include <cuda_bf16.h>
#include <cstdint>
#include <math.h>

#define L_TOT 65536
#define QD 64
#define C 32
#define VD 64
#define BLK 512
#define HALF 256
#define NB 128
#define QT 128
#define CHK 128

// ---------------- global scratch ----------------
// q/k: per position, 32 u32 = 64 bf16: b32[0:16)=hi(ch pairs), [16:32)=lo.
// q pre-scaled by 1/sqrt(C).
__device__ uint32_t g_q32[L_TOT * 32];
__device__ uint32_t g_k32[L_TOT * 32];
// v: ch-major bf16 hi/lo: [ch][l]
__device__ __nv_bfloat16 g_vhi[C * L_TOT];
__device__ __nv_bfloat16 g_vlo[C * L_TOT];

// ---------------- PTX helpers ----------------
__device__ __forceinline__ void cp16(uint32_t dst, const void* src, bool v) {
    int sz = v ? 16 : 0;
    asm volatile("cp.async.cg.shared.global [%0], [%1], 16, %2;\n"
                 :: "r"(dst), "l"(src), "r"(sz));
}
__device__ __forceinline__ void cp_commit() {
    asm volatile("cp.async.commit_group;\n" ::: "memory");
}
__device__ __forceinline__ void cp_wait0() {
    asm volatile("cp.async.wait_group 0;\n" ::: "memory");
}
// bf16 m16n8k16 row.col mma, fp32 accumulate
__device__ __forceinline__ void mma16816(float* c, const uint32_t* a,
                                         uint32_t b0, uint32_t b1) {
    asm volatile(
        "mma.sync.aligned.m16n8k16.row.col.f32.bf16.bf16.f32 "
        "{%0,%1,%2,%3}, {%4,%5,%6,%7}, {%8,%9}, {%0,%1,%2,%3};"
        : "+f"(c[0]), "+f"(c[1]), "+f"(c[2]), "+f"(c[3])
        : "r"(a[0]), "r"(a[1]), "r"(a[2]), "r"(a[3]), "r"(b0), "r"(b1));
}
// ldmatrix x4: four 8x8 b16 matrices; lanes 8m..8m+7 give row addrs of matrix m
__device__ __forceinline__ void ldsm_x4(uint32_t& r0, uint32_t& r1,
                                        uint32_t& r2, uint32_t& r3, uint32_t a) {
    asm volatile("ldmatrix.sync.aligned.m8n8.x4.shared.b16 {%0,%1,%2,%3}, [%4];"
                 : "=r"(r0), "=r"(r1), "=r"(r2), "=r"(r3) : "r"(a));
}
__device__ __forceinline__ uint32_t packbf2(float x, float y) {
    __nv_bfloat162 h = __floats2bfloat162_rn(x, y);
    return *reinterpret_cast<uint32_t*>(&h);
}

// ---------------- smem layout (att kernel, bytes) ----------------
#define SM_BOS     0        // 64 f32
#define SM_MW      256      // 2 x 128 f32
#define SM_WOS     1280     // 2048 f32
#define SM_K0      9472     // 128 rows x 144B
#define SM_K1      27904
#define SM_VHI0    46336    // 32 rows x 272B
#define SM_VLO0    55040
#define SM_VHI1    63744
#define SM_VLO1    72448
#define SM_OS      81152    // 128 x 33 f32
#define SMEM_ATT   98048

#define KSTRIDE32  36       // 144B row in b32
#define VSTRIDE32  68       // 272B row in b32

// ---------------------------------------------------------------------------
// Kernel 1: QKV projection -> split-bf16 scratch.
// grid = (L/256, 3): blockIdx.y selects projection (0=q,1=k,2=v).
// x1 loaded inline (no xv staging array -> low regs, high occupancy).
// ---------------------------------------------------------------------------
#define SMEM_PROJ 42112
__global__ __launch_bounds__(256) void proj_kernel(
    const float* __restrict__ x1,
    const float* __restrict__ Wq, const float* __restrict__ bq,
    const float* __restrict__ Wk, const float* __restrict__ bk,
    const float* __restrict__ Wv, const float* __restrict__ bv)
{
    extern __shared__ __align__(16) char psm[];
    float* sW = (float*)psm;                          // [d][c] 64x32
    float* sb = (float*)(psm + 8192);                 // 32
    uint32_t (*sRow)[33] = reinterpret_cast<uint32_t(*)[33]>(psm + 8320);
    __nv_bfloat16 (*sV)[256] = reinterpret_cast<__nv_bfloat16(*)[256]>(psm + 8320);

    int tid = threadIdx.x;
    int p = blockIdx.y;
    const float* W = (p == 0) ? Wq : (p == 1) ? Wk : Wv;
    const float* b = (p == 0) ? bq : (p == 1) ? bk : bv;

    for (int i = tid; i < QD * C; i += 256) {
        int d = i >> 5, c = i & 31;
        sW[i] = W[c * QD + d];
    }
    if (tid < C) sb[tid] = b[tid];
    __syncthreads();

    int l = blockIdx.x * 256 + tid;

    float acc[C];
#pragma unroll
    for (int c = 0; c < C; c++) acc[c] = sb[c];
#pragma unroll 16
    for (int d = 0; d < QD; d++) {
        float x = x1[(ptrdiff_t)d * L_TOT + l];
#pragma unroll
        for (int c4 = 0; c4 < C; c4 += 4) {
            float4 wv = *reinterpret_cast<const float4*>(&sW[d * C + c4]);
            acc[c4 + 0] += wv.x * x;
            acc[c4 + 1] += wv.y * x;
            acc[c4 + 2] += wv.z * x;
            acc[c4 + 3] += wv.w * x;
        }
    }

    int base = blockIdx.x * 256;
    if (p < 2) {
        float s = (p == 0) ? 0.17677669529663687f : 1.0f;
#pragma unroll
        for (int w2 = 0; w2 < 16; w2++) {
            float a0 = acc[2 * w2] * s, a1 = acc[2 * w2 + 1] * s;
            __nv_bfloat162 hh = __floats2bfloat162_rn(a0, a1);
            float l0 = a0 - __low2float(hh);
            float l1 = a1 - __high2float(hh);
            sRow[tid][w2]      = *reinterpret_cast<uint32_t*>(&hh);
            sRow[tid][16 + w2] = packbf2(l0, l1);
        }
        __syncthreads();
        uint32_t* g = (p == 0) ? g_q32 : g_k32;
        for (int i = tid; i < 8192; i += 256)
            g[(ptrdiff_t)(base + (i >> 5)) * 32 + (i & 31)] = sRow[i >> 5][i & 31];
    } else {
        // stage V hi through smem -> coalesced u32 global stores
#pragma unroll
        for (int c = 0; c < C; c++)
            sV[c][tid] = __float2bfloat16_rn(acc[c]);
        __syncthreads();
        for (int i = tid; i < 4096; i += 256) {
            int ch = i >> 7, u = i & 127;
            *reinterpret_cast<uint32_t*>(&g_vhi[(ptrdiff_t)ch * L_TOT + base + 2 * u]) =
                reinterpret_cast<const uint32_t*>(&sV[ch][0])[u];
        }
        __syncthreads();
        // lo pass
#pragma unroll
        for (int c = 0; c < C; c++) {
            __nv_bfloat16 hi = __float2bfloat16_rn(acc[c]);
            sV[c][tid] = __float2bfloat16_rn(acc[c] - __bfloat162float(hi));
        }
        __syncthreads();
        for (int i = tid; i < 4096; i += 256) {
            int ch = i >> 7, u = i & 127;
            *reinterpret_cast<uint32_t*>(&g_vlo[(ptrdiff_t)ch * L_TOT + base + 2 * u]) =
                reinterpret_cast<const uint32_t*>(&sV[ch][0])[u];
        }
    }
}

// ---------------------------------------------------------------------------
// preload K/V/mask chunk (cp.async, zero-fill OOB)
// ---------------------------------------------------------------------------
__device__ __forceinline__ void preload_chunk(
    uint32_t uK, uint32_t uVhi, uint32_t uVlo, uint32_t uMw,
    int kg0, int tid, const float* __restrict__ mask)
{
    // K: 128 rows x 8 granules (row = 64 bf16 hi|lo, 128B data, 144B stride)
#pragma unroll
    for (int i = tid; i < 1024; i += 256) {
        int r = i >> 3, g = i & 7;
        int gk = kg0 + r;
        bool v = (gk >= 0 && gk < L_TOT);
        cp16(uK + (uint32_t)(r * 144 + g * 16), &g_k32[(ptrdiff_t)gk * 32 + g * 4], v);
    }
    // V hi/lo: 32 ch rows x 16 granules (128 keys bf16 = 256B data, 272B stride)
#pragma unroll
    for (int i = tid; i < 512; i += 256) {
        int ch = i >> 4, g = i & 15;
        int gk = kg0 + g * 8;
        bool v = (gk >= 0 && gk < L_TOT);
        cp16(uVhi + (uint32_t)(ch * 272 + g * 16), &g_vhi[(ptrdiff_t)ch * L_TOT + gk], v);
        cp16(uVlo + (uint32_t)(ch * 272 + g * 16), &g_vlo[(ptrdiff_t)ch * L_TOT + gk], v);
    }
    if (tid < 32) {
        int gk = kg0 + tid * 4;
        bool v = (gk >= 0 && gk < L_TOT);
        cp16(uMw + (uint32_t)(tid * 16), &mask[gk], v);
    }
}

// ---------------------------------------------------------------------------
// Kernel 2: mma.sync split-bf16 sliding-window attention, ldmatrix fragments,
// 64-key half-chunks, 2 CTAs/SM.
// ---------------------------------------------------------------------------
__global__ __launch_bounds__(256, 2) void att_kernel(
    const float* __restrict__ mask,
    const float* __restrict__ Wo, const float* __restrict__ bo,
    float* __restrict__ out)
{
    extern __shared__ __align__(16) char smem[];
    uint32_t su = (uint32_t)__cvta_generic_to_shared(smem);
    float* bos = (float*)(smem + SM_BOS);
    float* Wos = (float*)(smem + SM_WOS);
    float* Osf = (float*)(smem + SM_OS);

    int tid = threadIdx.x;
    int wid = tid >> 5, lane = tid & 31;
    int lq = lane >> 2;          // quad row 0..7
    int lc = lane & 3;           // quad col 0..3
    int nb = blockIdx.x >> 2;
    int t  = blockIdx.x & 3;
    int qbase  = nb * BLK + t * QT;
    int wstart = nb * BLK - HALF;
    int nch = 3 + t;

    for (int i = tid; i < VD * C; i += 256) {
        int o = i >> 5, ch = i & 31;
        Wos[ch * VD + o] = Wo[i];
    }
    if (tid < VD) bos[tid] = bo[tid];

    preload_chunk(su + SM_K0, su + SM_VHI0, su + SM_VLO0, su + SM_MW,
                  wstart, tid, mask);
    cp_commit();

    // Q fragments (register-resident): [hl][kstep][4]
    uint32_t qa[2][2][4];
    {
        const uint32_t* q0 = &g_q32[(ptrdiff_t)(qbase + 16 * wid + lq) * 32];
        const uint32_t* q8 = q0 + 8 * 32;
#pragma unroll
        for (int hl = 0; hl < 2; hl++) {
            int base = hl * 16;
#pragma unroll
            for (int s = 0; s < 2; s++) {
                qa[hl][s][0] = q0[base + s * 8 + lc];
                qa[hl][s][1] = q8[base + s * 8 + lc];
                qa[hl][s][2] = q0[base + s * 8 + lc + 4];
                qa[hl][s][3] = q8[base + s * 8 + lc + 4];
            }
        }
    }

    // per-lane ldmatrix row-address bases (lane%8 = row, lane/8 = matrix idx)
    const uint32_t kmrow = (uint32_t)((lane & 7) * 144 + (lane >> 3) * 16);
    const uint32_t vmrow = (uint32_t)((lane & 7) * 272 + (lane >> 3) * 16);

    const int row0 = 16 * wid + lq;
    const int lim0 = HALF + t * QT + row0;
    const int lim8 = lim0 + 8;
    const int limw = HALF + t * QT + 16 * wid + 15;

    float oacc[4][4];
#pragma unroll
    for (int nt = 0; nt < 4; nt++)
#pragma unroll
        for (int j = 0; j < 4; j++) oacc[nt][j] = 0.f;
    float z0 = 0.f, z1 = 0.f;

    for (int ci = 0; ci < nch; ci++) {
        int buf = ci & 1;
        uint32_t kb = su + (buf ? SM_K1 : SM_K0) + kmrow;
        uint32_t vhb = su + (buf ? SM_VHI1 : SM_VHI0) + vmrow;
        uint32_t vlb = su + (buf ? SM_VLO1 : SM_VLO0) + vmrow;
        const float* mw = (const float*)(smem + SM_MW + buf * 512);

        cp_wait0();
        __syncthreads();
        if (ci + 1 < nch) {
            int b2 = (ci + 1) & 1;
            preload_chunk(su + (b2 ? SM_K1 : SM_K0),
                          su + (b2 ? SM_VHI1 : SM_VHI0),
                          su + (b2 ? SM_VLO1 : SM_VLO0),
                          su + SM_MW + b2 * 512,
                          wstart + (ci + 1) * CHK, tid, mask);
            cp_commit();
        }

        // process chunk in two 64-key halves (register economy -> occupancy)
#pragma unroll
        for (int h = 0; h < 2; h++) {
            int jrem = (limw - ci * CHK - 64 * h) / 8 + 1;  // warp-uniform
            if (jrem <= 0) break;
            int jh = jrem > 8 ? 8 : jrem;
            int uh = (jh + 1) >> 1;

            // ---- GEMM1: e = Q.K^T (hi.hi + lo.hi + hi.lo) ----
            float e[8][4];
#pragma unroll
            for (int j = 0; j < 8; j++)
#pragma unroll
                for (int x = 0; x < 4; x++) e[j][x] = 0.f;
#pragma unroll
            for (int j = 0; j < 8; j++) {
                if (j < jh) {
                    uint32_t ka = kb + (uint32_t)((64 * h + 8 * j) * 144);
                    uint32_t a0, a1, a2, a3, b0, b1, b2, b3;
                    ldsm_x4(a0, a1, a2, a3, ka);        // hi: s0b0 s0b1 s1b0 s1b1
                    ldsm_x4(b0, b1, b2, b3, ka + 64);   // lo
                    mma16816(e[j], qa[0][0], a0, a1);
                    mma16816(e[j], qa[1][0], a0, a1);
                    mma16816(e[j], qa[0][0], b0, b1);
                    mma16816(e[j], qa[0][1], a2, a3);
                    mma16816(e[j], qa[1][1], a2, a3);
                    mma16816(e[j], qa[0][1], b2, b3);
                }
            }

            // ---- softmax (no-max), in-register P hi/lo ----
            uint32_t phi[4][4], plo[4][4];
#pragma unroll
            for (int u = 0; u < 4; u++) {
                if (u < uh) {
#pragma unroll
                    for (int hf = 0; hf < 2; hf++) {
                        int j = 2 * u + hf;
                        float p0 = 0.f, p1 = 0.f, p2 = 0.f, p3 = 0.f;
                        if (j < jh) {
                            int mwi = 64 * h + j * 8 + lc * 2;
                            int cg  = ci * CHK + mwi;
                            float m0 = mw[mwi], m1 = mw[mwi + 1];
                            bool v0 = (cg     <= lim0) && (m0 != 0.f);
                            bool v1 = (cg + 1 <= lim0) && (m1 != 0.f);
                            bool v2 = (cg     <= lim8) && (m0 != 0.f);
                            bool v3 = (cg + 1 <= lim8) && (m1 != 0.f);
                            p0 = v0 ? __expf(e[j][0]) : 0.f;
                            p1 = v1 ? __expf(e[j][1]) : 0.f;
                            p2 = v2 ? __expf(e[j][2]) : 0.f;
                            p3 = v3 ? __expf(e[j][3]) : 0.f;
                            z0 += p0 + p1;
                            z1 += p2 + p3;
                        }
                        __nv_bfloat162 h01 = __floats2bfloat162_rn(p0, p1);
                        __nv_bfloat162 h23 = __floats2bfloat162_rn(p2, p3);
                        phi[u][2 * hf + 0] = *reinterpret_cast<uint32_t*>(&h01);
                        phi[u][2 * hf + 1] = *reinterpret_cast<uint32_t*>(&h23);
                        plo[u][2 * hf + 0] = packbf2(p0 - __low2float(h01),
                                                     p1 - __high2float(h01));
                        plo[u][2 * hf + 1] = packbf2(p2 - __low2float(h23),
                                                     p3 - __high2float(h23));
                    }
                }
            }

            // ---- GEMM2: O += P.V^T (phi.vhi + plo.vhi + phi.vlo) ----
#pragma unroll
            for (int nt = 0; nt < 4; nt++) {
                uint32_t va = vhb + (uint32_t)(nt * 8 * 272 + h * 128);
                uint32_t vb = vlb + (uint32_t)(nt * 8 * 272 + h * 128);
#pragma unroll
                for (int w = 0; w < 2; w++) {
                    if (2 * w < uh) {
                        uint32_t h0, h1, h2, h3, l0, l1, l2, l3;
                        ldsm_x4(h0, h1, h2, h3, va + w * 64);  // u=2w b0 b1, u=2w+1 b0 b1
                        ldsm_x4(l0, l1, l2, l3, vb + w * 64);
                        mma16816(oacc[nt], phi[2 * w], h0, h1);
                        mma16816(oacc[nt], plo[2 * w], h0, h1);
                        mma16816(oacc[nt], phi[2 * w], l0, l1);
                        if (2 * w + 1 < uh) {
                            mma16816(oacc[nt], phi[2 * w + 1], h2, h3);
                            mma16816(oacc[nt], plo[2 * w + 1], h2, h3);
                            mma16816(oacc[nt], phi[2 * w + 1], l2, l3);
                        }
                    }
                }
            }
        }
    }

    // ---- Z reduction within quads ----
    z0 += __shfl_xor_sync(0xffffffffu, z0, 1);
    z0 += __shfl_xor_sync(0xffffffffu, z0, 2);
    z1 += __shfl_xor_sync(0xffffffffu, z1, 1);
    z1 += __shfl_xor_sync(0xffffffffu, z1, 2);
    float invz0 = 1.f / z0, invz8 = 1.f / z1;

    // ---- Os = relu(O/Z) -> smem ----
#pragma unroll
    for (int nt = 0; nt < 4; nt++) {
        int ch = nt * 8 + lc * 2;
        Osf[row0 * 33 + ch]           = fmaxf(oacc[nt][0] * invz0, 0.f);
        Osf[row0 * 33 + ch + 1]       = fmaxf(oacc[nt][1] * invz0, 0.f);
        Osf[(row0 + 8) * 33 + ch]     = fmaxf(oacc[nt][2] * invz8, 0.f);
        Osf[(row0 + 8) * 33 + ch + 1] = fmaxf(oacc[nt][3] * invz8, 0.f);
    }
    __syncthreads();

    // ---- output projection: y = Wo . Os + bo, * mask ----
    int oh   = tid >> 7;
    int q    = tid & 127;
    int qpos = qbase + q;
    float mv = mask[qpos];
    float y[32];
#pragma unroll
    for (int j = 0; j < 32; j++) y[j] = bos[oh * 32 + j];
#pragma unroll 8
    for (int ch = 0; ch < C; ch++) {
        float ov = Osf[q * 33 + ch];
#pragma unroll
        for (int j4 = 0; j4 < 32; j4 += 4) {
            float4 w4 = *reinterpret_cast<const float4*>(&Wos[ch * VD + oh * 32 + j4]);
            y[j4 + 0] += w4.x * ov;
            y[j4 + 1] += w4.y * ov;
            y[j4 + 2] += w4.z * ov;
            y[j4 + 3] += w4.w * ov;
        }
    }
#pragma unroll
    for (int j = 0; j < 32; j++)
        out[(ptrdiff_t)(oh * 32 + j) * L_TOT + qpos] = y[j] * mv;
}

// ---------------------------------------------------------------------------
extern "C" void kernel_launch(void* const* d_in, const int* in_sizes, int n_in,
                              void* d_out, int out_size)
{
    const float* x1   = (const float*)d_in[0];
    const float* mask = (const float*)d_in[2];
    const float* Wq   = (const float*)d_in[3];
    const float* bq   = (const float*)d_in[4];
    const float* Wk   = (const float*)d_in[5];
    const float* bk   = (const float*)d_in[6];
    const float* Wv   = (const float*)d_in[7];
    const float* bv   = (const float*)d_in[8];
    const float* Wo   = (const float*)d_in[9];
    const float* bo   = (const float*)d_in[10];
    float* out = (float*)d_out;

    cudaFuncSetAttribute(proj_kernel, cudaFuncAttributeMaxDynamicSharedMemorySize, SMEM_PROJ);
    proj_kernel<<<dim3(L_TOT / 256, 3), 256, SMEM_PROJ>>>(x1, Wq, bq, Wk, bk, Wv, bv);

    cudaFuncSetAttribute(att_kernel, cudaFuncAttributeMaxDynamicSharedMemorySize, SMEM_ATT);
    att_kernel<<<NB * 4, 256, SMEM_ATT>>>(mask, Wo, bo, out);
}